// round 3
// baseline (speedup 1.0000x reference)
#include <cuda_runtime.h>
#include <math_constants.h>

#define BB 4
#define TE 1024
#define TD 512
#define HH 128
#define DTILE 14
#define NTILES 37      // ceil(512/14); 4*37 = 148 CTAs = 1 full wave on GB300
#define TCHUNK 32
#define NCHUNK (TE / TCHUNK)        // 32
#define NTHREADS (DTILE * 32)       // 448

// Scratch (statically allocated; no cudaMalloc allowed anywhere)
__device__ float g_Ws[BB * TE * HH];   // enc @ W_a
__device__ float g_Uh[BB * TD * HH];   // dec @ U_a

__device__ __forceinline__ float tanh_fast(float x) {
    float y;
    asm("tanh.approx.f32 %0, %1;" : "=f"(y) : "f"(x));
    return y;
}

// ---------------------------------------------------------------------------
// Stage 1: row-wise projection  out[r][k] = sum_h in[r][h] * W[h][k]
// One warp per row; lane owns 4 contiguous output columns. W stays L1/L2-hot.
// ---------------------------------------------------------------------------
__global__ __launch_bounds__(256) void proj_kernel(
    const float* __restrict__ in, const float* __restrict__ W,
    int nrows, int which /* 0 -> g_Ws, 1 -> g_Uh */)
{
    int w    = threadIdx.x >> 5;
    int lane = threadIdx.x & 31;
    int row  = blockIdx.x * 8 + w;
    if (row >= nrows) return;

    float* out = which ? g_Uh : g_Ws;

    const float4* in4 = (const float4*)(in + (long)row * HH);
    const float4* W4  = (const float4*)W;

    float4 acc = make_float4(0.f, 0.f, 0.f, 0.f);
    #pragma unroll 4
    for (int h4 = 0; h4 < HH / 4; ++h4) {
        float4 a  = in4[h4];
        float4 w0 = W4[(h4 * 4 + 0) * 32 + lane];
        acc.x += a.x * w0.x; acc.y += a.x * w0.y; acc.z += a.x * w0.z; acc.w += a.x * w0.w;
        float4 w1 = W4[(h4 * 4 + 1) * 32 + lane];
        acc.x += a.y * w1.x; acc.y += a.y * w1.y; acc.z += a.y * w1.z; acc.w += a.y * w1.w;
        float4 w2 = W4[(h4 * 4 + 2) * 32 + lane];
        acc.x += a.z * w2.x; acc.y += a.z * w2.y; acc.z += a.z * w2.z; acc.w += a.z * w2.w;
        float4 w3 = W4[(h4 * 4 + 3) * 32 + lane];
        acc.x += a.w * w3.x; acc.y += a.w * w3.y; acc.z += a.w * w3.z; acc.w += a.w * w3.w;
    }
    ((float4*)out)[(long)row * 32 + lane] = acc;
}

// ---------------------------------------------------------------------------
// Stage 2: fused energies + online softmax + context + weight write-back.
// CTA = (b, tile of 14 d's). Warp w owns d = tile*14 + w; lane owns
// h = 4*lane..4*lane+3. t processed in chunks of 32 staged through smem.
// After the butterfly reduce every lane holds the logit; lane tt keeps the
// logit for t = chunk*32 + tt in a per-thread local array -> the final e
// write is fully coalesced and no smem logit buffer is needed.
// ---------------------------------------------------------------------------
__global__ __launch_bounds__(NTHREADS) void attn_main_kernel(
    const float* __restrict__ enc,   // [B, TE, H]
    const float* __restrict__ Va,    // [H]
    float* __restrict__ c_out,       // [B, TD, H]
    float* __restrict__ e_out)       // [B, TD, TE]
{
    __shared__ float4 ws_s [TCHUNK * HH / 4];   // 16 KB
    __shared__ float4 enc_s[TCHUNK * HH / 4];   // 16 KB

    const int tid  = threadIdx.x;
    const int w    = tid >> 5;
    const int lane = tid & 31;
    const int b    = blockIdx.y;
    const int d    = blockIdx.x * DTILE + w;
    const bool valid = (d < TD);

    const float4 v4 = ((const float4*)Va)[lane];
    float4 uh4 = make_float4(0.f, 0.f, 0.f, 0.f);
    if (valid)
        uh4 = ((const float4*)g_Uh)[(b * TD + d) * (HH / 4) + lane];

    float m = -CUDART_INF_F;
    float l = 0.f;
    float4 cacc = make_float4(0.f, 0.f, 0.f, 0.f);
    float lgbuf[NCHUNK];   // per-thread logit slice (local mem, L1-resident)

    for (int chunk = 0; chunk < NCHUNK; ++chunk) {
        const int t0 = chunk * TCHUNK;
        __syncthreads();
        {
            const float4* wsrc = (const float4*)(g_Ws + (long)(b * TE + t0) * HH);
            const float4* esrc = (const float4*)(enc  + (long)(b * TE + t0) * HH);
            #pragma unroll
            for (int i = tid; i < TCHUNK * HH / 4; i += NTHREADS) {
                ws_s[i]  = wsrc[i];
                enc_s[i] = esrc[i];
            }
        }
        __syncthreads();

        float mylg = 0.f;
        #pragma unroll 4
        for (int tt = 0; tt < TCHUNK; ++tt) {
            float4 ws = ws_s[tt * 32 + lane];
            float h0 = tanh_fast(ws.x + uh4.x);
            float h1 = tanh_fast(ws.y + uh4.y);
            float h2 = tanh_fast(ws.z + uh4.z);
            float h3 = tanh_fast(ws.w + uh4.w);
            float part = v4.x * h0;
            part = fmaf(v4.y, h1, part);
            part = fmaf(v4.z, h2, part);
            part = fmaf(v4.w, h3, part);
            // butterfly reduce over h (lanes) -> all lanes hold the sum
            part += __shfl_xor_sync(0xffffffffu, part, 16);
            part += __shfl_xor_sync(0xffffffffu, part, 8);
            part += __shfl_xor_sync(0xffffffffu, part, 4);
            part += __shfl_xor_sync(0xffffffffu, part, 2);
            part += __shfl_xor_sync(0xffffffffu, part, 1);
            const float lgt = part;

            if (tt == lane) mylg = lgt;      // lane tt owns t = t0 + tt

            if (lgt > m) {                   // warp-uniform branch
                float corr = __expf(m - lgt);   // first iter: exp(-inf) = 0
                l *= corr;
                cacc.x *= corr; cacc.y *= corr; cacc.z *= corr; cacc.w *= corr;
                m = lgt;
            }
            float p = __expf(lgt - m);
            l += p;
            float4 ev = enc_s[tt * 32 + lane];
            cacc.x = fmaf(p, ev.x, cacc.x);
            cacc.y = fmaf(p, ev.y, cacc.y);
            cacc.z = fmaf(p, ev.z, cacc.z);
            cacc.w = fmaf(p, ev.w, cacc.w);
        }
        lgbuf[chunk] = mylg;
    }

    if (!valid) return;

    const float invl = 1.0f / l;

    // context vector [H], lane owns 4 h's -> coalesced float4 store
    float4 co;
    co.x = cacc.x * invl; co.y = cacc.y * invl;
    co.z = cacc.z * invl; co.w = cacc.w * invl;
    ((float4*)c_out)[(b * TD + d) * (HH / 4) + lane] = co;

    // attention weights: lane tt wrote chunk*32+tt -> coalesced per chunk
    float* erow = e_out + (long)(b * TD + d) * TE;
    #pragma unroll
    for (int chunk = 0; chunk < NCHUNK; ++chunk) {
        erow[chunk * TCHUNK + lane] = __expf(lgbuf[chunk] - m) * invl;
    }
}

// ---------------------------------------------------------------------------
extern "C" void kernel_launch(void* const* d_in, const int* in_sizes, int n_in,
                              void* d_out, int out_size)
{
    const float* enc = (const float*)d_in[0];   // [B, TE, H]
    const float* dec = (const float*)d_in[1];   // [B, TD, H]
    const float* W_a = (const float*)d_in[2];   // [H, H]
    const float* U_a = (const float*)d_in[3];   // [H, H]
    const float* V_a = (const float*)d_in[4];   // [H, 1]

    float* c_out = (float*)d_out;                        // [B, TD, H]
    float* e_out = (float*)d_out + (long)BB * TD * HH;   // [B, TD, TE]

    // Stage 1: projections into __device__ scratch
    proj_kernel<<<(BB * TE + 7) / 8, 256>>>(enc, W_a, BB * TE, 0);
    proj_kernel<<<(BB * TD + 7) / 8, 256>>>(dec, U_a, BB * TD, 1);

    // Stage 2: fused attention (148 CTAs = exactly one wave, 32 KB static smem)
    dim3 grid(NTILES, BB);
    attn_main_kernel<<<grid, NTHREADS>>>(enc, V_a, c_out, e_out);
}

// round 6
// speedup vs baseline: 1.5741x; 1.5741x over previous
#include <cuda_runtime.h>
#include <math_constants.h>

#define BB 4
#define TE 1024
#define TD 512
#define HH 128
#define DTILE 14
#define NTILES 37      // ceil(512/14); 4*37 = 148 CTAs = 1 full wave
#define TCHUNK 32
#define NCHUNK (TE / TCHUNK)        // 32
#define NTHREADS (DTILE * 32)       // 448
#define ROWPAD 33                   // float4s per padded smem row (132 floats)

// Scratch (statically allocated; no cudaMalloc allowed anywhere)
__device__ float g_Ws[BB * TE * HH];   // enc @ W_a
__device__ float g_Uh[BB * TD * HH];   // dec @ U_a

__device__ __forceinline__ float tanh_fast(float x) {
    float y;
    asm("tanh.approx.f32 %0, %1;" : "=f"(y) : "f"(x));
    return y;
}

// ---------------------------------------------------------------------------
// Stage 1 (fused): rows 0..4095 -> g_Ws = enc @ W_a; rows 4096..6143 -> g_Uh.
// 4 rows per warp share the W register loads (4x less L1 traffic, 4x ILP).
// ---------------------------------------------------------------------------
__global__ __launch_bounds__(256) void proj_all_kernel(
    const float* __restrict__ enc, const float* __restrict__ dec,
    const float* __restrict__ Wa,  const float* __restrict__ Ua)
{
    const int w    = threadIdx.x >> 5;
    const int lane = threadIdx.x & 31;
    const int gw   = blockIdx.x * 8 + w;      // 0..1535
    int r0 = gw * 4;

    const float* in; const float* W; float* out;
    if (r0 < BB * TE) { in = enc; W = Wa; out = g_Ws; }
    else              { r0 -= BB * TE; in = dec; W = Ua; out = g_Uh; }

    const float4* in4 = (const float4*)in;
    const float4* W4  = (const float4*)W;

    float4 acc0 = make_float4(0.f,0.f,0.f,0.f);
    float4 acc1 = acc0, acc2 = acc0, acc3 = acc0;

    #pragma unroll 8
    for (int h = 0; h < HH; ++h) {
        float4 wv = W4[h * 32 + lane];          // W[h][4lane..4lane+3]
        float a0 = ((const float*)&in4[(r0 + 0) * 32])[h];  // warp-uniform
        float a1 = ((const float*)&in4[(r0 + 1) * 32])[h];
        float a2 = ((const float*)&in4[(r0 + 2) * 32])[h];
        float a3 = ((const float*)&in4[(r0 + 3) * 32])[h];
        acc0.x = fmaf(a0, wv.x, acc0.x); acc0.y = fmaf(a0, wv.y, acc0.y);
        acc0.z = fmaf(a0, wv.z, acc0.z); acc0.w = fmaf(a0, wv.w, acc0.w);
        acc1.x = fmaf(a1, wv.x, acc1.x); acc1.y = fmaf(a1, wv.y, acc1.y);
        acc1.z = fmaf(a1, wv.z, acc1.z); acc1.w = fmaf(a1, wv.w, acc1.w);
        acc2.x = fmaf(a2, wv.x, acc2.x); acc2.y = fmaf(a2, wv.y, acc2.y);
        acc2.z = fmaf(a2, wv.z, acc2.z); acc2.w = fmaf(a2, wv.w, acc2.w);
        acc3.x = fmaf(a3, wv.x, acc3.x); acc3.y = fmaf(a3, wv.y, acc3.y);
        acc3.z = fmaf(a3, wv.z, acc3.z); acc3.w = fmaf(a3, wv.w, acc3.w);
    }
    ((float4*)out)[(r0 + 0) * 32 + lane] = acc0;
    ((float4*)out)[(r0 + 1) * 32 + lane] = acc1;
    ((float4*)out)[(r0 + 2) * 32 + lane] = acc2;
    ((float4*)out)[(r0 + 3) * 32 + lane] = acc3;
}

// ---------------------------------------------------------------------------
// Stage 2: fused energies + online softmax + context.
// CTA = (b, tile of 14 d's); warp w owns d = tile*14 + w.
// Phase 1 (lane = t): each lane computes one t's logit serially over h —
//   NO shuffles, all tanh independent -> MUFU pipelines fully.
// Softmax (lane = t): one warp exp per 32 t's; 5 SHFLs per chunk.
// Context (lane = h): p broadcast from smem, cacc += p * enc.
// Global->smem staging is register-double-buffered: chunk k+1 is prefetched
// into registers while chunk k computes, hiding L2 latency.
// ---------------------------------------------------------------------------
__global__ __launch_bounds__(NTHREADS) void attn_main_kernel(
    const float* __restrict__ enc,   // [B, TE, H]
    const float* __restrict__ Va,    // [H]
    float* __restrict__ c_out,       // [B, TD, H]
    float* __restrict__ e_out)       // [B, TD, TE]
{
    __shared__ float4 ws_s [TCHUNK * ROWPAD];        // padded: conflict-free lane=t reads
    __shared__ float4 enc_s[TCHUNK * ROWPAD];
    __shared__ float4 uh_s [DTILE * (HH / 4)];       // per-warp U_h row
    __shared__ float4 v_s  [HH / 4];
    __shared__ float  p_s  [DTILE * TCHUNK];         // per-warp softmax weights

    const int tid  = threadIdx.x;
    const int w    = tid >> 5;
    const int lane = tid & 31;
    const int b    = blockIdx.y;
    const int d    = blockIdx.x * DTILE + w;
    const bool valid = (d < TD);

    // one-time staging of uh (per warp) and v
    {
        float4 uh = make_float4(0.f,0.f,0.f,0.f);
        if (valid) uh = ((const float4*)g_Uh)[(b * TD + d) * 32 + lane];
        uh_s[w * 32 + lane] = uh;
        if (w == 0) v_s[lane] = ((const float4*)Va)[lane];
    }

    float m = -CUDART_INF_F;
    float l_part = 0.f;                       // per-lane partial of l
    float4 cacc = make_float4(0.f,0.f,0.f,0.f);
    float lgbuf[NCHUNK];                      // lane's logit per chunk (t = chunk*32+lane)

    const float4* wsrc_b = (const float4*)(g_Ws + (long)b * TE * HH);
    const float4* esrc_b = (const float4*)(enc  + (long)b * TE * HH);

    // Each thread owns up to 3 of the 1024 float4 slots per array.
    const int s0 = tid;                 // < 1024 always
    const int s1 = tid + NTHREADS;      // max 895 < 1024
    const int s2 = tid + 2 * NTHREADS;  // valid only for tid < 128
    const bool has2 = (s2 < TCHUNK * 32);

    float4 rw0, rw1, rw2, re0, re1, re2;

    // prefetch chunk 0
    {
        const float4* wsrc = wsrc_b;        // t0 = 0
        const float4* esrc = esrc_b;
        rw0 = wsrc[s0]; re0 = esrc[s0];
        rw1 = wsrc[s1]; re1 = esrc[s1];
        if (has2) { rw2 = wsrc[s2]; re2 = esrc[s2]; }
    }

    #pragma unroll 1
    for (int chunk = 0; chunk < NCHUNK; ++chunk) {
        __syncthreads();   // previous chunk's smem consumers are done
        // store registers -> padded smem
        {
            int r0s = s0 >> 5, c0s = s0 & 31;
            ws_s [r0s * ROWPAD + c0s] = rw0;  enc_s[r0s * ROWPAD + c0s] = re0;
            int r1s = s1 >> 5, c1s = s1 & 31;
            ws_s [r1s * ROWPAD + c1s] = rw1;  enc_s[r1s * ROWPAD + c1s] = re1;
            if (has2) {
                int r2s = s2 >> 5, c2s = s2 & 31;
                ws_s [r2s * ROWPAD + c2s] = rw2;  enc_s[r2s * ROWPAD + c2s] = re2;
            }
        }
        __syncthreads();

        // prefetch chunk+1 (loads in flight while we compute below)
        if (chunk + 1 < NCHUNK) {
            const float4* wsrc = wsrc_b + (chunk + 1) * TCHUNK * 32;
            const float4* esrc = esrc_b + (chunk + 1) * TCHUNK * 32;
            rw0 = wsrc[s0]; re0 = esrc[s0];
            rw1 = wsrc[s1]; re1 = esrc[s1];
            if (has2) { rw2 = wsrc[s2]; re2 = esrc[s2]; }
        }

        // ---- Phase 1: lane = t. logit[lane] = sum_h v[h]*tanh(ws+uh) ----
        float4 a0 = make_float4(0.f,0.f,0.f,0.f);
        const float4* wsrow = ws_s + lane * ROWPAD;
        const float4* uhrow = uh_s + w * 32;
        #pragma unroll 8
        for (int hq = 0; hq < 32; ++hq) {
            float4 ws = wsrow[hq];          // conflict-free (pad 132 floats)
            float4 uh = uhrow[hq];          // broadcast
            float4 vv = v_s[hq];            // broadcast
            a0.x = fmaf(vv.x, tanh_fast(ws.x + uh.x), a0.x);
            a0.y = fmaf(vv.y, tanh_fast(ws.y + uh.y), a0.y);
            a0.z = fmaf(vv.z, tanh_fast(ws.z + uh.z), a0.z);
            a0.w = fmaf(vv.w, tanh_fast(ws.w + uh.w), a0.w);
        }
        const float lgt = (a0.x + a0.y) + (a0.z + a0.w);
        lgbuf[chunk] = lgt;

        // ---- Online softmax over this chunk (warp scope) ----
        float cm = lgt;
        cm = fmaxf(cm, __shfl_xor_sync(0xffffffffu, cm, 16));
        cm = fmaxf(cm, __shfl_xor_sync(0xffffffffu, cm, 8));
        cm = fmaxf(cm, __shfl_xor_sync(0xffffffffu, cm, 4));
        cm = fmaxf(cm, __shfl_xor_sync(0xffffffffu, cm, 2));
        cm = fmaxf(cm, __shfl_xor_sync(0xffffffffu, cm, 1));
        if (cm > m) {                         // warp-uniform
            float corr = __expf(m - cm);      // first chunk: exp(-inf) = 0
            l_part *= corr;
            cacc.x *= corr; cacc.y *= corr; cacc.z *= corr; cacc.w *= corr;
            m = cm;
        }
        float p = __expf(lgt - m);            // ONE MUFU for 32 t's
        l_part += p;
        p_s[w * 32 + lane] = p;
        __syncwarp();

        // ---- Context: lane = h-quad. cacc += p[tt] * enc[tt][h] ----
        #pragma unroll 8
        for (int tt = 0; tt < TCHUNK; ++tt) {
            float pt = p_s[w * 32 + tt];      // broadcast
            float4 ev = enc_s[tt * ROWPAD + lane];
            cacc.x = fmaf(pt, ev.x, cacc.x);
            cacc.y = fmaf(pt, ev.y, cacc.y);
            cacc.z = fmaf(pt, ev.z, cacc.z);
            cacc.w = fmaf(pt, ev.w, cacc.w);
        }
        __syncwarp();                         // p_s reads done before next overwrite
    }

    // final l: reduce per-lane partials
    float l = l_part;
    l += __shfl_xor_sync(0xffffffffu, l, 16);
    l += __shfl_xor_sync(0xffffffffu, l, 8);
    l += __shfl_xor_sync(0xffffffffu, l, 4);
    l += __shfl_xor_sync(0xffffffffu, l, 2);
    l += __shfl_xor_sync(0xffffffffu, l, 1);

    if (!valid) return;
    const float invl = 1.0f / l;

    // context vector: lane owns 4 h's -> coalesced float4 store
    float4 co;
    co.x = cacc.x * invl; co.y = cacc.y * invl;
    co.z = cacc.z * invl; co.w = cacc.w * invl;
    ((float4*)c_out)[(b * TD + d) * 32 + lane] = co;

    // attention weights: lane owns t = chunk*32 + lane -> coalesced per chunk
    float* erow = e_out + (long)(b * TD + d) * TE;
    #pragma unroll 1
    for (int chunk = 0; chunk < NCHUNK; ++chunk)
        erow[chunk * TCHUNK + lane] = __expf(lgbuf[chunk] - m) * invl;
}

// ---------------------------------------------------------------------------
extern "C" void kernel_launch(void* const* d_in, const int* in_sizes, int n_in,
                              void* d_out, int out_size)
{
    const float* enc = (const float*)d_in[0];   // [B, TE, H]
    const float* dec = (const float*)d_in[1];   // [B, TD, H]
    const float* W_a = (const float*)d_in[2];   // [H, H]
    const float* U_a = (const float*)d_in[3];   // [H, H]
    const float* V_a = (const float*)d_in[4];   // [H, 1]

    float* c_out = (float*)d_out;                        // [B, TD, H]
    float* e_out = (float*)d_out + (long)BB * TD * HH;   // [B, TD, TE]

    // Stage 1: both projections in one launch (1536 warps / 8 per CTA)
    proj_all_kernel<<<(BB * (TE + TD)) / 4 / 8, 256>>>(enc, dec, W_a, U_a);

    // Stage 2: fused attention (148 CTAs = one wave, ~43 KB static smem)
    dim3 grid(NTILES, BB);
    attn_main_kernel<<<grid, NTHREADS>>>(enc, V_a, c_out, e_out);
}

// round 7
// speedup vs baseline: 1.7122x; 1.0877x over previous
#include <cuda_runtime.h>
#include <math_constants.h>

#define BB 4
#define TE 1024
#define TD 512
#define HH 128
#define DTILE 14        // d's per CTA (7 warps x 2)
#define NW 7            // warps per CTA
#define NTILES 37       // ceil(512/14); 4*37 = 148 CTAs = 1 full wave
#define TCHUNK 32
#define NCHUNK (TE / TCHUNK)        // 32
#define NTHREADS (NW * 32)          // 224
#define ROWPAD 33                   // float4s per padded smem row

// Scratch (statically allocated; no cudaMalloc allowed anywhere)
__device__ float g_Ws[BB * TE * HH];   // enc @ W_a
__device__ float g_Uh[BB * TD * HH];   // dec @ U_a

__device__ __forceinline__ float tanh_fast(float x) {
    float y;
    asm("tanh.approx.f32 %0, %1;" : "=f"(y) : "f"(x));
    return y;
}

// ---------------------------------------------------------------------------
// Stage 1 (fused): rows 0..4095 -> g_Ws = enc @ W_a; rows 4096..6143 -> g_Uh.
// 4 rows per warp; a-loads vectorized (float4 per 4 h) -> 256 LDG.128/warp.
// ---------------------------------------------------------------------------
__global__ __launch_bounds__(256) void proj_all_kernel(
    const float* __restrict__ enc, const float* __restrict__ dec,
    const float* __restrict__ Wa,  const float* __restrict__ Ua)
{
    const int w    = threadIdx.x >> 5;
    const int lane = threadIdx.x & 31;
    const int gw   = blockIdx.x * 8 + w;      // 0..1535
    int r0 = gw * 4;

    const float* in; const float* W; float* out;
    if (r0 < BB * TE) { in = enc; W = Wa; out = g_Ws; }
    else              { r0 -= BB * TE; in = dec; W = Ua; out = g_Uh; }

    const float4* in4 = (const float4*)in;
    const float4* W4  = (const float4*)W;

    float4 acc0 = make_float4(0.f,0.f,0.f,0.f);
    float4 acc1 = acc0, acc2 = acc0, acc3 = acc0;

    #pragma unroll 4
    for (int hg = 0; hg < HH / 4; ++hg) {     // group of 4 h's
        float4 a0 = in4[(r0 + 0) * 32 + hg];  // warp-uniform .128 loads
        float4 a1 = in4[(r0 + 1) * 32 + hg];
        float4 a2 = in4[(r0 + 2) * 32 + hg];
        float4 a3 = in4[(r0 + 3) * 32 + hg];
        #pragma unroll
        for (int j = 0; j < 4; ++j) {
            float4 wv = W4[(hg * 4 + j) * 32 + lane];
            float s0 = (j == 0) ? a0.x : (j == 1) ? a0.y : (j == 2) ? a0.z : a0.w;
            float s1 = (j == 0) ? a1.x : (j == 1) ? a1.y : (j == 2) ? a1.z : a1.w;
            float s2 = (j == 0) ? a2.x : (j == 1) ? a2.y : (j == 2) ? a2.z : a2.w;
            float s3 = (j == 0) ? a3.x : (j == 1) ? a3.y : (j == 2) ? a3.z : a3.w;
            acc0.x = fmaf(s0, wv.x, acc0.x); acc0.y = fmaf(s0, wv.y, acc0.y);
            acc0.z = fmaf(s0, wv.z, acc0.z); acc0.w = fmaf(s0, wv.w, acc0.w);
            acc1.x = fmaf(s1, wv.x, acc1.x); acc1.y = fmaf(s1, wv.y, acc1.y);
            acc1.z = fmaf(s1, wv.z, acc1.z); acc1.w = fmaf(s1, wv.w, acc1.w);
            acc2.x = fmaf(s2, wv.x, acc2.x); acc2.y = fmaf(s2, wv.y, acc2.y);
            acc2.z = fmaf(s2, wv.z, acc2.z); acc2.w = fmaf(s2, wv.w, acc2.w);
            acc3.x = fmaf(s3, wv.x, acc3.x); acc3.y = fmaf(s3, wv.y, acc3.y);
            acc3.z = fmaf(s3, wv.z, acc3.z); acc3.w = fmaf(s3, wv.w, acc3.w);
        }
    }
    ((float4*)out)[(r0 + 0) * 32 + lane] = acc0;
    ((float4*)out)[(r0 + 1) * 32 + lane] = acc1;
    ((float4*)out)[(r0 + 2) * 32 + lane] = acc2;
    ((float4*)out)[(r0 + 3) * 32 + lane] = acc3;
}

// ---------------------------------------------------------------------------
// Stage 2: fused energies + online softmax + context, 2 d's per warp.
// Warp w owns d0 = tile*14 + w and d1 = d0 + 7. One ws smem read feeds 8
// tanh (2 d's); one enc LDG feeds 8 context FMAs. enc is read direct from
// global (lane = h layout is coalesced & L1-hot across the 7 warps).
// ---------------------------------------------------------------------------
__global__ __launch_bounds__(NTHREADS) void attn_main_kernel(
    const float* __restrict__ enc,   // [B, TE, H]
    const float* __restrict__ Va,    // [H]
    float* __restrict__ c_out,       // [B, TD, H]
    float* __restrict__ e_out)       // [B, TD, TE]
{
    __shared__ float4 ws_s[TCHUNK * ROWPAD];      // padded: conflict-free lane=t reads
    __shared__ float4 uh_s[DTILE * (HH / 4)];     // rows w (d0) and w+7 (d1)
    __shared__ float4 v_s [HH / 4];
    __shared__ float  p_s [NW][2 * TCHUNK];       // per-warp softmax weights (d0|d1)

    const int tid  = threadIdx.x;
    const int w    = tid >> 5;
    const int lane = tid & 31;
    const int b    = blockIdx.y;
    const int d0   = blockIdx.x * DTILE + w;      // always < 512 (max 510)
    const int d1   = d0 + NW;
    const bool valid1 = (d1 < TD);

    // one-time staging of uh rows (per warp) and v
    {
        uh_s[w * 32 + lane] = ((const float4*)g_Uh)[(b * TD + d0) * 32 + lane];
        float4 u1 = make_float4(0.f,0.f,0.f,0.f);
        if (valid1) u1 = ((const float4*)g_Uh)[(b * TD + d1) * 32 + lane];
        uh_s[(w + NW) * 32 + lane] = u1;
        if (w == 0) v_s[lane] = ((const float4*)Va)[lane];
    }

    float m0 = -CUDART_INF_F, m1 = -CUDART_INF_F;
    float l0 = 0.f, l1 = 0.f;                     // per-lane partials
    float4 cacc0 = make_float4(0.f,0.f,0.f,0.f);
    float4 cacc1 = cacc0;
    float lgbuf0[NCHUNK], lgbuf1[NCHUNK];         // lane's logits (local mem)

    const float4* wsrc_b = (const float4*)(g_Ws + (long)b * TE * HH);
    const float4* esrc_b = (const float4*)(enc  + (long)b * TE * HH);

    // staging: 1024 float4 slots, 5 per thread (last guarded)
    const int s0 = tid, s1 = tid + 224, s2 = tid + 448, s3 = tid + 672, s4 = tid + 896;
    const bool has4 = (s4 < TCHUNK * 32);
    float4 r0v, r1v, r2v, r3v, r4v;

    // prefetch chunk 0
    r0v = wsrc_b[s0]; r1v = wsrc_b[s1]; r2v = wsrc_b[s2]; r3v = wsrc_b[s3];
    if (has4) r4v = wsrc_b[s4];

    #pragma unroll 1
    for (int chunk = 0; chunk < NCHUNK; ++chunk) {
        __syncthreads();   // previous chunk's ws_s consumers done
        ws_s[(s0 >> 5) * ROWPAD + (s0 & 31)] = r0v;
        ws_s[(s1 >> 5) * ROWPAD + (s1 & 31)] = r1v;
        ws_s[(s2 >> 5) * ROWPAD + (s2 & 31)] = r2v;
        ws_s[(s3 >> 5) * ROWPAD + (s3 & 31)] = r3v;
        if (has4) ws_s[(s4 >> 5) * ROWPAD + (s4 & 31)] = r4v;
        __syncthreads();

        // prefetch chunk+1 (in flight during compute)
        if (chunk + 1 < NCHUNK) {
            const float4* nsrc = wsrc_b + (chunk + 1) * (TCHUNK * 32);
            r0v = nsrc[s0]; r1v = nsrc[s1]; r2v = nsrc[s2]; r3v = nsrc[s3];
            if (has4) r4v = nsrc[s4];
        }

        // ---- Phase 1: lane = t. Two logits per lane (d0, d1) ----
        float4 a0 = make_float4(0.f,0.f,0.f,0.f);
        float4 a1 = a0;
        const float4* wsrow = ws_s + lane * ROWPAD;
        const float4* u0row = uh_s + w * 32;
        const float4* u1row = uh_s + (w + NW) * 32;
        #pragma unroll 8
        for (int hq = 0; hq < 32; ++hq) {
            float4 ws = wsrow[hq];          // 4-cyc conflict-free
            float4 u0 = u0row[hq];          // broadcast
            float4 u1 = u1row[hq];          // broadcast
            float4 vv = v_s[hq];            // broadcast
            a0.x = fmaf(vv.x, tanh_fast(ws.x + u0.x), a0.x);
            a1.x = fmaf(vv.x, tanh_fast(ws.x + u1.x), a1.x);
            a0.y = fmaf(vv.y, tanh_fast(ws.y + u0.y), a0.y);
            a1.y = fmaf(vv.y, tanh_fast(ws.y + u1.y), a1.y);
            a0.z = fmaf(vv.z, tanh_fast(ws.z + u0.z), a0.z);
            a1.z = fmaf(vv.z, tanh_fast(ws.z + u1.z), a1.z);
            a0.w = fmaf(vv.w, tanh_fast(ws.w + u0.w), a0.w);
            a1.w = fmaf(vv.w, tanh_fast(ws.w + u1.w), a1.w);
        }
        const float lgt0 = (a0.x + a0.y) + (a0.z + a0.w);
        const float lgt1 = (a1.x + a1.y) + (a1.z + a1.w);
        lgbuf0[chunk] = lgt0;
        lgbuf1[chunk] = lgt1;

        // ---- Online softmax (warp scope, both d's) ----
        float cm0 = lgt0, cm1 = lgt1;
        #pragma unroll
        for (int off = 16; off > 0; off >>= 1) {
            cm0 = fmaxf(cm0, __shfl_xor_sync(0xffffffffu, cm0, off));
            cm1 = fmaxf(cm1, __shfl_xor_sync(0xffffffffu, cm1, off));
        }
        if (cm0 > m0) {
            float corr = __expf(m0 - cm0);    // first chunk: exp(-inf) = 0
            l0 *= corr;
            cacc0.x *= corr; cacc0.y *= corr; cacc0.z *= corr; cacc0.w *= corr;
            m0 = cm0;
        }
        if (cm1 > m1) {
            float corr = __expf(m1 - cm1);
            l1 *= corr;
            cacc1.x *= corr; cacc1.y *= corr; cacc1.z *= corr; cacc1.w *= corr;
            m1 = cm1;
        }
        float p0 = __expf(lgt0 - m0);
        float p1 = __expf(lgt1 - m1);
        l0 += p0; l1 += p1;
        p_s[w][lane]      = p0;
        p_s[w][32 + lane] = p1;
        __syncwarp();

        // ---- Context: lane = h-quad; enc direct LDG (L1-hot) ----
        const float4* encrow = esrc_b + chunk * (TCHUNK * 32);
        #pragma unroll 8
        for (int tt = 0; tt < TCHUNK; ++tt) {
            float pt0 = p_s[w][tt];
            float pt1 = p_s[w][32 + tt];
            float4 ev = encrow[tt * 32 + lane];
            cacc0.x = fmaf(pt0, ev.x, cacc0.x);
            cacc0.y = fmaf(pt0, ev.y, cacc0.y);
            cacc0.z = fmaf(pt0, ev.z, cacc0.z);
            cacc0.w = fmaf(pt0, ev.w, cacc0.w);
            cacc1.x = fmaf(pt1, ev.x, cacc1.x);
            cacc1.y = fmaf(pt1, ev.y, cacc1.y);
            cacc1.z = fmaf(pt1, ev.z, cacc1.z);
            cacc1.w = fmaf(pt1, ev.w, cacc1.w);
        }
        __syncwarp();   // p_s consumed before next chunk overwrites
    }

    // reduce per-lane l partials
    #pragma unroll
    for (int off = 16; off > 0; off >>= 1) {
        l0 += __shfl_xor_sync(0xffffffffu, l0, off);
        l1 += __shfl_xor_sync(0xffffffffu, l1, off);
    }
    const float invl0 = 1.0f / l0;
    const float invl1 = 1.0f / l1;

    // context vectors (coalesced float4 stores)
    {
        float4 co;
        co.x = cacc0.x * invl0; co.y = cacc0.y * invl0;
        co.z = cacc0.z * invl0; co.w = cacc0.w * invl0;
        ((float4*)c_out)[(b * TD + d0) * 32 + lane] = co;
        if (valid1) {
            co.x = cacc1.x * invl1; co.y = cacc1.y * invl1;
            co.z = cacc1.z * invl1; co.w = cacc1.w * invl1;
            ((float4*)c_out)[(b * TD + d1) * 32 + lane] = co;
        }
    }

    // attention weights (lane owns t = chunk*32 + lane -> coalesced)
    float* erow0 = e_out + (long)(b * TD + d0) * TE;
    float* erow1 = e_out + (long)(b * TD + d1) * TE;
    #pragma unroll 1
    for (int chunk = 0; chunk < NCHUNK; ++chunk) {
        erow0[chunk * TCHUNK + lane] = __expf(lgbuf0[chunk] - m0) * invl0;
        if (valid1)
            erow1[chunk * TCHUNK + lane] = __expf(lgbuf1[chunk] - m1) * invl1;
    }
}

// ---------------------------------------------------------------------------
extern "C" void kernel_launch(void* const* d_in, const int* in_sizes, int n_in,
                              void* d_out, int out_size)
{
    const float* enc = (const float*)d_in[0];   // [B, TE, H]
    const float* dec = (const float*)d_in[1];   // [B, TD, H]
    const float* W_a = (const float*)d_in[2];   // [H, H]
    const float* U_a = (const float*)d_in[3];   // [H, H]
    const float* V_a = (const float*)d_in[4];   // [H, 1]

    float* c_out = (float*)d_out;                        // [B, TD, H]
    float* e_out = (float*)d_out + (long)BB * TD * HH;   // [B, TD, TE]

    // Stage 1: both projections (192 CTAs x 8 warps x 4 rows = 6144 rows)
    proj_all_kernel<<<(BB * (TE + TD)) / 4 / 8, 256>>>(enc, dec, W_a, U_a);

    // Stage 2: fused attention (148 CTAs = one wave, ~26 KB static smem)
    dim3 grid(NTILES, BB);
    attn_main_kernel<<<grid, NTHREADS>>>(enc, V_a, c_out, e_out);
}

// round 8
// speedup vs baseline: 2.1566x; 1.2596x over previous
#include <cuda_runtime.h>
#include <math_constants.h>

#define BB 4
#define TE 1024
#define TD 512
#define HH 128
#define DTILE 14        // d's per CTA: 7 pairs, each owned by 2 warps (t-split)
#define NPAIR 7
#define NW 14           // warps per CTA
#define NTILES 37       // ceil(512/14); 4*37 = 148 CTAs = 1 full wave
#define TCHUNK 32
#define NCHUNK 32
#define HCHUNK 16       // chunks per warp-half
#define NTHREADS (NW * 32)          // 448
#define ROWPAD 33                   // float4s per padded smem row

// smem byte layout (static, 45056 B < 48 KB)
#define WSA_OFF 0
#define WSB_OFF 16896
#define UH_OFF  33792
#define V_OFF   40960
#define P_OFF   41472
#define SMEM_BYTES 45056

// Scratch (statically allocated; no cudaMalloc allowed anywhere)
__device__ float g_Ws[BB * TE * HH];   // enc @ W_a
__device__ float g_Uh[BB * TD * HH];   // dec @ U_a

__device__ __forceinline__ float tanh_fast(float x) {
    float y;
    asm("tanh.approx.f32 %0, %1;" : "=f"(y) : "f"(x));
    return y;
}

// ---------------------------------------------------------------------------
// Stage 1 (fused): rows 0..4095 -> g_Ws = enc @ W_a; rows 4096..6143 -> g_Uh.
// 4 rows per warp; a-loads vectorized (float4 per 4 h).
// ---------------------------------------------------------------------------
__global__ __launch_bounds__(256) void proj_all_kernel(
    const float* __restrict__ enc, const float* __restrict__ dec,
    const float* __restrict__ Wa,  const float* __restrict__ Ua)
{
    const int w    = threadIdx.x >> 5;
    const int lane = threadIdx.x & 31;
    const int gw   = blockIdx.x * 8 + w;      // 0..1535
    int r0 = gw * 4;

    const float* in; const float* W; float* out;
    if (r0 < BB * TE) { in = enc; W = Wa; out = g_Ws; }
    else              { r0 -= BB * TE; in = dec; W = Ua; out = g_Uh; }

    const float4* in4 = (const float4*)in;
    const float4* W4  = (const float4*)W;

    float4 acc0 = make_float4(0.f,0.f,0.f,0.f);
    float4 acc1 = acc0, acc2 = acc0, acc3 = acc0;

    #pragma unroll 4
    for (int hg = 0; hg < HH / 4; ++hg) {     // group of 4 h's
        float4 a0 = in4[(r0 + 0) * 32 + hg];  // warp-uniform .128 loads
        float4 a1 = in4[(r0 + 1) * 32 + hg];
        float4 a2 = in4[(r0 + 2) * 32 + hg];
        float4 a3 = in4[(r0 + 3) * 32 + hg];
        #pragma unroll
        for (int j = 0; j < 4; ++j) {
            float4 wv = W4[(hg * 4 + j) * 32 + lane];
            float s0 = (j == 0) ? a0.x : (j == 1) ? a0.y : (j == 2) ? a0.z : a0.w;
            float s1 = (j == 0) ? a1.x : (j == 1) ? a1.y : (j == 2) ? a1.z : a1.w;
            float s2 = (j == 0) ? a2.x : (j == 1) ? a2.y : (j == 2) ? a2.z : a2.w;
            float s3 = (j == 0) ? a3.x : (j == 1) ? a3.y : (j == 2) ? a3.z : a3.w;
            acc0.x = fmaf(s0, wv.x, acc0.x); acc0.y = fmaf(s0, wv.y, acc0.y);
            acc0.z = fmaf(s0, wv.z, acc0.z); acc0.w = fmaf(s0, wv.w, acc0.w);
            acc1.x = fmaf(s1, wv.x, acc1.x); acc1.y = fmaf(s1, wv.y, acc1.y);
            acc1.z = fmaf(s1, wv.z, acc1.z); acc1.w = fmaf(s1, wv.w, acc1.w);
            acc2.x = fmaf(s2, wv.x, acc2.x); acc2.y = fmaf(s2, wv.y, acc2.y);
            acc2.z = fmaf(s2, wv.z, acc2.z); acc2.w = fmaf(s2, wv.w, acc2.w);
            acc3.x = fmaf(s3, wv.x, acc3.x); acc3.y = fmaf(s3, wv.y, acc3.y);
            acc3.z = fmaf(s3, wv.z, acc3.z); acc3.w = fmaf(s3, wv.w, acc3.w);
        }
    }
    ((float4*)out)[(r0 + 0) * 32 + lane] = acc0;
    ((float4*)out)[(r0 + 1) * 32 + lane] = acc1;
    ((float4*)out)[(r0 + 2) * 32 + lane] = acc2;
    ((float4*)out)[(r0 + 3) * 32 + lane] = acc3;
}

// ---------------------------------------------------------------------------
// Stage 2: fused energies + online softmax + context.
// 14 warps; warps j and j+7 both own d-pair (d0 = tile*14+j, d1 = d0+7):
// warp j covers chunks 0..15 (buffer A), warp j+7 covers chunks 16..31
// (buffer B). Flash-style partials merged across the warp pair at the end.
// ---------------------------------------------------------------------------
__global__ __launch_bounds__(NTHREADS) void attn_main_kernel(
    const float* __restrict__ enc,   // [B, TE, H]
    const float* __restrict__ Va,    // [H]
    float* __restrict__ c_out,       // [B, TD, H]
    float* __restrict__ e_out)       // [B, TD, TE]
{
    __shared__ __align__(16) char sm[SMEM_BYTES];
    float4* wsA  = (float4*)(sm + WSA_OFF);   // 32 rows x ROWPAD
    float4* wsB  = (float4*)(sm + WSB_OFF);
    float4* uh_s = (float4*)(sm + UH_OFF);    // 14 rows x 32
    float4* v_s  = (float4*)(sm + V_OFF);
    float*  p_s  = (float*) (sm + P_OFF);     // [14][64]

    const int tid  = threadIdx.x;
    const int w    = tid >> 5;
    const int lane = tid & 31;
    const int half = (w >= NPAIR);
    const int j    = half ? w - NPAIR : w;    // pair index 0..6
    const int b    = blockIdx.y;
    const int dbase = blockIdx.x * DTILE;
    const int d0   = dbase + j;               // max 510
    const int d1   = d0 + NPAIR;
    const bool valid1 = (d1 < TD);
    const int cbase = half * HCHUNK;          // this warp's first chunk

    // one-time staging: uh row w (d = dbase + w), and v
    {
        int dw = dbase + w;
        float4 u = make_float4(0.f,0.f,0.f,0.f);
        if (dw < TD) u = ((const float4*)g_Uh)[(b * TD + dw) * 32 + lane];
        uh_s[w * 32 + lane] = u;
        if (w == 0) v_s[lane] = ((const float4*)Va)[lane];
    }

    float m0 = -CUDART_INF_F, m1 = -CUDART_INF_F;
    float l0 = 0.f, l1 = 0.f;                  // per-lane partials
    float4 cacc0 = make_float4(0.f,0.f,0.f,0.f);
    float4 cacc1 = cacc0;
    float lgbuf0[HCHUNK], lgbuf1[HCHUNK];

    const float4* wsrc_b = (const float4*)(g_Ws + (long)b * TE * HH);
    const float4* esrc_b = (const float4*)(enc  + (long)b * TE * HH);

    // staging: 2048 float4 slots/iter (A: chunk k, B: chunk k+16), 5/thread
    const int s0 = tid, s1 = tid + 448, s2 = tid + 896, s3 = tid + 1344, s4 = tid + 1792;
    const bool has4 = (s4 < 2048);
    float4 r0v, r1v, r2v, r3v, r4v;

    // global index for slot s at chunk-pair k: (s<1024 ? k : k+16)*1024 + (s&1023)
    #define SLOT_SRC(s, k) ((((s) < 1024 ? (k) : (k) + HCHUNK) << 10) + ((s) & 1023))
    #define SLOT_DST(s) (((s) < 1024 ? wsA : wsB)[((((s) & 1023) >> 5) * ROWPAD) + ((s) & 31)])

    // prefetch chunk-pair 0
    r0v = wsrc_b[SLOT_SRC(s0, 0)]; r1v = wsrc_b[SLOT_SRC(s1, 0)];
    r2v = wsrc_b[SLOT_SRC(s2, 0)]; r3v = wsrc_b[SLOT_SRC(s3, 0)];
    if (has4) r4v = wsrc_b[SLOT_SRC(s4, 0)];

    const float4* mybuf = half ? wsB : wsA;
    const float4* u0row = uh_s + j * 32;
    const float4* u1row = uh_s + (j + NPAIR) * 32;
    float* prow = p_s + w * 64;

    #pragma unroll 1
    for (int k = 0; k < HCHUNK; ++k) {
        __syncthreads();   // previous iteration's consumers done
        SLOT_DST(s0) = r0v; SLOT_DST(s1) = r1v; SLOT_DST(s2) = r2v; SLOT_DST(s3) = r3v;
        if (has4) SLOT_DST(s4) = r4v;
        __syncthreads();

        // prefetch next chunk-pair
        if (k + 1 < HCHUNK) {
            r0v = wsrc_b[SLOT_SRC(s0, k + 1)]; r1v = wsrc_b[SLOT_SRC(s1, k + 1)];
            r2v = wsrc_b[SLOT_SRC(s2, k + 1)]; r3v = wsrc_b[SLOT_SRC(s3, k + 1)];
            if (has4) r4v = wsrc_b[SLOT_SRC(s4, k + 1)];
        }

        // ---- Phase 1: lane = t. Two logits per lane (d0, d1) ----
        float4 a0 = make_float4(0.f,0.f,0.f,0.f);
        float4 a1 = a0;
        const float4* wsrow = mybuf + lane * ROWPAD;
        #pragma unroll 8
        for (int hq = 0; hq < 32; ++hq) {
            float4 ws = wsrow[hq];          // conflict-free
            float4 u0 = u0row[hq];          // broadcast
            float4 u1 = u1row[hq];          // broadcast
            float4 vv = v_s[hq];            // broadcast
            a0.x = fmaf(vv.x, tanh_fast(ws.x + u0.x), a0.x);
            a1.x = fmaf(vv.x, tanh_fast(ws.x + u1.x), a1.x);
            a0.y = fmaf(vv.y, tanh_fast(ws.y + u0.y), a0.y);
            a1.y = fmaf(vv.y, tanh_fast(ws.y + u1.y), a1.y);
            a0.z = fmaf(vv.z, tanh_fast(ws.z + u0.z), a0.z);
            a1.z = fmaf(vv.z, tanh_fast(ws.z + u1.z), a1.z);
            a0.w = fmaf(vv.w, tanh_fast(ws.w + u0.w), a0.w);
            a1.w = fmaf(vv.w, tanh_fast(ws.w + u1.w), a1.w);
        }
        const float lgt0 = (a0.x + a0.y) + (a0.z + a0.w);
        const float lgt1 = (a1.x + a1.y) + (a1.z + a1.w);
        lgbuf0[k] = lgt0;
        lgbuf1[k] = lgt1;

        // ---- Online softmax (warp scope, both d's) ----
        float cm0 = lgt0, cm1 = lgt1;
        #pragma unroll
        for (int off = 16; off > 0; off >>= 1) {
            cm0 = fmaxf(cm0, __shfl_xor_sync(0xffffffffu, cm0, off));
            cm1 = fmaxf(cm1, __shfl_xor_sync(0xffffffffu, cm1, off));
        }
        if (cm0 > m0) {
            float corr = __expf(m0 - cm0);    // first iter: exp(-inf) = 0
            l0 *= corr;
            cacc0.x *= corr; cacc0.y *= corr; cacc0.z *= corr; cacc0.w *= corr;
            m0 = cm0;
        }
        if (cm1 > m1) {
            float corr = __expf(m1 - cm1);
            l1 *= corr;
            cacc1.x *= corr; cacc1.y *= corr; cacc1.z *= corr; cacc1.w *= corr;
            m1 = cm1;
        }
        float p0 = __expf(lgt0 - m0);
        float p1 = __expf(lgt1 - m1);
        l0 += p0; l1 += p1;
        prow[lane]      = p0;
        prow[32 + lane] = p1;
        __syncwarp();

        // ---- Context: lane = h-quad; enc via direct LDG (L1-hot) ----
        const float4* encrow = esrc_b + (cbase + k) * (TCHUNK * 32);
        #pragma unroll 8
        for (int tt = 0; tt < TCHUNK; ++tt) {
            float pt0 = prow[tt];
            float pt1 = prow[32 + tt];
            float4 ev = encrow[tt * 32 + lane];
            cacc0.x = fmaf(pt0, ev.x, cacc0.x);
            cacc0.y = fmaf(pt0, ev.y, cacc0.y);
            cacc0.z = fmaf(pt0, ev.z, cacc0.z);
            cacc0.w = fmaf(pt0, ev.w, cacc0.w);
            cacc1.x = fmaf(pt1, ev.x, cacc1.x);
            cacc1.y = fmaf(pt1, ev.y, cacc1.y);
            cacc1.z = fmaf(pt1, ev.z, cacc1.z);
            cacc1.w = fmaf(pt1, ev.w, cacc1.w);
        }
        __syncwarp();   // prow consumed before next iteration overwrites
    }

    // reduce per-lane l partials within the warp
    #pragma unroll
    for (int off = 16; off > 0; off >>= 1) {
        l0 += __shfl_xor_sync(0xffffffffu, l0, off);
        l1 += __shfl_xor_sync(0xffffffffu, l1, off);
    }

    // ---- Cross-warp merge of (m, l, C) between warp j and j+7 ----
    // Reuse the (now dead) wsA staging region for merge buffers.
    __syncthreads();
    float*  mg  = (float*)(sm + WSA_OFF);          // [14][4]: m0,m1,l0,l1
    float4* mgc = (float4*)(sm + WSA_OFF + 256);   // [14][64] float4: cacc0|cacc1
    if (lane == 0) {
        mg[w * 4 + 0] = m0; mg[w * 4 + 1] = m1;
        mg[w * 4 + 2] = l0; mg[w * 4 + 3] = l1;
    }
    mgc[w * 64 + lane]      = cacc0;
    mgc[w * 64 + 32 + lane] = cacc1;
    __syncthreads();

    const int partner = half ? w - NPAIR : w + NPAIR;
    float pm0 = mg[partner * 4 + 0], pm1 = mg[partner * 4 + 1];
    float pl0 = mg[partner * 4 + 2], pl1 = mg[partner * 4 + 3];
    float4 pc0 = mgc[partner * 64 + lane];
    float4 pc1 = mgc[partner * 64 + 32 + lane];

    const float M0 = fmaxf(m0, pm0), M1 = fmaxf(m1, pm1);
    const float sa0 = __expf(m0 - M0), sb0 = __expf(pm0 - M0);
    const float sa1 = __expf(m1 - M1), sb1 = __expf(pm1 - M1);
    const float L0 = l0 * sa0 + pl0 * sb0;
    const float L1 = l1 * sa1 + pl1 * sb1;
    const float invl0 = 1.0f / L0;
    const float invl1 = 1.0f / L1;

    // combined context store: lower warp only (values identical on both)
    if (!half) {
        float4 co;
        co.x = (cacc0.x * sa0 + pc0.x * sb0) * invl0;
        co.y = (cacc0.y * sa0 + pc0.y * sb0) * invl0;
        co.z = (cacc0.z * sa0 + pc0.z * sb0) * invl0;
        co.w = (cacc0.w * sa0 + pc0.w * sb0) * invl0;
        ((float4*)c_out)[(b * TD + d0) * 32 + lane] = co;
        if (valid1) {
            co.x = (cacc1.x * sa1 + pc1.x * sb1) * invl1;
            co.y = (cacc1.y * sa1 + pc1.y * sb1) * invl1;
            co.z = (cacc1.z * sa1 + pc1.z * sb1) * invl1;
            co.w = (cacc1.w * sa1 + pc1.w * sb1) * invl1;
            ((float4*)c_out)[(b * TD + d1) * 32 + lane] = co;
        }
    }

    // attention weights: each warp writes its own 16 chunks with final (M, L)
    float* erow0 = e_out + (long)(b * TD + d0) * TE + cbase * TCHUNK;
    float* erow1 = e_out + (long)(b * TD + d1) * TE + cbase * TCHUNK;
    #pragma unroll 1
    for (int k = 0; k < HCHUNK; ++k) {
        erow0[k * TCHUNK + lane] = __expf(lgbuf0[k] - M0) * invl0;
        if (valid1)
            erow1[k * TCHUNK + lane] = __expf(lgbuf1[k] - M1) * invl1;
    }
}

// ---------------------------------------------------------------------------
extern "C" void kernel_launch(void* const* d_in, const int* in_sizes, int n_in,
                              void* d_out, int out_size)
{
    const float* enc = (const float*)d_in[0];   // [B, TE, H]
    const float* dec = (const float*)d_in[1];   // [B, TD, H]
    const float* W_a = (const float*)d_in[2];   // [H, H]
    const float* U_a = (const float*)d_in[3];   // [H, H]
    const float* V_a = (const float*)d_in[4];   // [H, 1]

    float* c_out = (float*)d_out;                        // [B, TD, H]
    float* e_out = (float*)d_out + (long)BB * TD * HH;   // [B, TD, TE]

    // Stage 1: both projections (192 CTAs x 8 warps x 4 rows = 6144 rows)
    proj_all_kernel<<<(BB * (TE + TD)) / 4 / 8, 256>>>(enc, dec, W_a, U_a);

    // Stage 2: fused attention (148 CTAs = one wave, 44 KB static smem)
    dim3 grid(NTILES, BB);
    attn_main_kernel<<<grid, NTHREADS>>>(enc, V_a, c_out, e_out);
}